// round 4
// baseline (speedup 1.0000x reference)
#include <cuda_runtime.h>
#include <cuda_bf16.h>

#define NMAX 50000
#define EMAX 800000
#define F_IN 128
#define F_OUT 64

// ---- device scratch (no allocations allowed) ----
__device__ float  g_h[NMAX * F_OUT];         // h = x @ W
__device__ float  g_as[NMAX];                // h . a1
__device__ float  g_ad[NMAX];                // h . a2
__device__ float  g_m[NMAX];                 // max(seg_max, 0)
__device__ float2 g_sumdeg[NMAX];            // {segment sum of exp, degree}
__device__ float  g_invd[NMAX];              // 1/denom
__device__ float  g_logit[EMAX];             // logit, then overwritten with exp_l
__device__ int    g_src[EMAX];               // normalized src indices (int32)
__device__ int    g_dst[EMAX];               // normalized dst indices (int32)
__device__ int    g_flag;                    // 0 = int64 edge buffer, nonzero = int32

// ---------------------------------------------------------------------------
// K0: zero the per-node accumulators + the dtype flag
// ---------------------------------------------------------------------------
__global__ void k_zero(int N) {
    int i = blockIdx.x * blockDim.x + threadIdx.x;
    if (i == 0) g_flag = 0;
    if (i < N) {
        g_m[i] = 0.f;
        g_sumdeg[i] = make_float2(0.f, 0.f);
    }
}

// ---------------------------------------------------------------------------
// K-detect: int64 vs int32 edge buffer (odd 32-bit words all zero => int64)
// ---------------------------------------------------------------------------
__global__ void k_detect(const unsigned int* __restrict__ raw) {
    int t = threadIdx.x;                    // 256 threads, 1 block
    if (raw[2 * t + 1] != 0u)
        atomicOr(&g_flag, 1);
}

// ---------------------------------------------------------------------------
// K-norm: materialize int32 src/dst regardless of source dtype.
// ---------------------------------------------------------------------------
__global__ void k_norm(const void* __restrict__ raw, int E) {
    int e = blockIdx.x * blockDim.x + threadIdx.x;
    if (e >= E) return;
    int s, d;
    if (g_flag == 0) {                      // int64 source
        const long long* p = (const long long*)raw;
        s = (int)p[e];
        d = (int)p[E + e];
    } else {                                // int32 source
        const int* p = (const int*)raw;
        s = p[e];
        d = p[E + e];
    }
    g_src[e] = s;
    g_dst[e] = d;
}

// ---------------------------------------------------------------------------
// K1: h = x @ W  via register-blocked f32x2 FMA (FFMA2).
// 256 threads, TILE_M = 128 rows, all 64 cols. Thread tile: 4 rows x 8 cols.
// K split into two 64-wide phases so the x-stage is half-size:
//   smem = Ws[128][64] (32KB, staged once) + xs[64][132] (33.8KB per phase)
//   = 66.5KB -> 3 blocks/SM, 24 warps/SM. Grid 391 fits in one wave (444).
// Per k per thread: 1 LDS.128 (4 a-rows) + 2 LDS.128 (8 b-cols as f32x2)
//                   + 4 dup-movs + 16 fma.rn.f32x2.
// ---------------------------------------------------------------------------
#define XS_PITCH 132   // 16B-aligned row starts for LDS.128 on the compute side

__global__ void __launch_bounds__(256, 3)
k_gemm(const float* __restrict__ x, const float* __restrict__ W, int N) {
    extern __shared__ float smem[];
    float* Ws = smem;                        // [128][64]
    float* xs = smem + F_IN * F_OUT;         // [64][XS_PITCH]
    int tid = threadIdx.x;

    // Stage all of W (row-major [k][64]) as float4
    const float4* W4 = (const float4*)W;
    #pragma unroll
    for (int i = tid; i < F_IN * F_OUT / 4; i += 256)
        ((float4*)Ws)[i] = W4[i];

    int row0 = blockIdx.x * 128;
    int trow = tid >> 3;         // 0..31
    int tcol = tid & 7;          // 0..7
    int r0 = trow * 4;
    int c0 = tcol * 8;

    unsigned long long acc[4][4];
    #pragma unroll
    for (int i = 0; i < 4; i++)
        #pragma unroll
        for (int j = 0; j < 4; j++) acc[i][j] = 0ULL;

    #pragma unroll
    for (int ph = 0; ph < 2; ph++) {
        __syncthreads();         // previous phase's reads done before overwrite
        // Stage 64 k-slices transposed: xs[kk][r]
        #pragma unroll
        for (int i = tid; i < 128 * 64; i += 256) {
            int r  = i >> 6;     // 0..127
            int kk = i & 63;     // coalesced along k
            int gr = row0 + r;
            float v = (gr < N) ? x[(size_t)gr * F_IN + ph * 64 + kk] : 0.f;
            xs[kk * XS_PITCH + r] = v;
        }
        __syncthreads();

        #pragma unroll 8
        for (int kk = 0; kk < 64; kk++) {
            const float* wrow = &Ws[(ph * 64 + kk) * F_OUT + c0];
            ulonglong2 b01 = *(const ulonglong2*)wrow;
            ulonglong2 b23 = *(const ulonglong2*)(wrow + 4);
            unsigned long long b0 = b01.x, b1 = b01.y, b2 = b23.x, b3 = b23.y;
            float4 a = *(const float4*)&xs[kk * XS_PITCH + r0];
            float av[4] = {a.x, a.y, a.z, a.w};
            #pragma unroll
            for (int i = 0; i < 4; i++) {
                unsigned long long a2;
                asm("mov.b64 %0, {%1, %1};" : "=l"(a2) : "f"(av[i]));
                asm("fma.rn.f32x2 %0, %1, %2, %0;" : "+l"(acc[i][0]) : "l"(a2), "l"(b0));
                asm("fma.rn.f32x2 %0, %1, %2, %0;" : "+l"(acc[i][1]) : "l"(a2), "l"(b1));
                asm("fma.rn.f32x2 %0, %1, %2, %0;" : "+l"(acc[i][2]) : "l"(a2), "l"(b2));
                asm("fma.rn.f32x2 %0, %1, %2, %0;" : "+l"(acc[i][3]) : "l"(a2), "l"(b3));
            }
        }
    }

    // Store 4 rows x 8 cols (2 x 16B per row)
    #pragma unroll
    for (int i = 0; i < 4; i++) {
        int row = row0 + r0 + i;
        if (row < N) {
            ulonglong2 s0; s0.x = acc[i][0]; s0.y = acc[i][1];
            ulonglong2 s1; s1.x = acc[i][2]; s1.y = acc[i][3];
            *(ulonglong2*)&g_h[(size_t)row * F_OUT + c0]     = s0;
            *(ulonglong2*)&g_h[(size_t)row * F_OUT + c0 + 4] = s1;
        }
    }
}

// ---------------------------------------------------------------------------
// K2: per-node attention coefficients: as = h.a1, ad = h.a2 (one warp/node)
// ---------------------------------------------------------------------------
__global__ void k_alpha(const float* __restrict__ att, int N) {
    int gt = blockIdx.x * blockDim.x + threadIdx.x;
    int node = gt >> 5;
    int lane = gt & 31;
    if (node >= N) return;
    float2 hv = *(const float2*)&g_h[(size_t)node * F_OUT + lane * 2];
    float a1x = att[lane * 2], a1y = att[lane * 2 + 1];
    float a2x = att[F_OUT + lane * 2], a2y = att[F_OUT + lane * 2 + 1];
    float s = hv.x * a1x + hv.y * a1y;
    float d = hv.x * a2x + hv.y * a2y;
    #pragma unroll
    for (int o = 16; o; o >>= 1) {
        s += __shfl_down_sync(0xFFFFFFFFu, s, o);
        d += __shfl_down_sync(0xFFFFFFFFu, d, o);
    }
    if (lane == 0) {
        g_as[node] = s;
        g_ad[node] = d;
    }
}

// ---------------------------------------------------------------------------
// K3: per-edge logit + segment max (atomicMax on int bits; m >= 0 invariant)
// ---------------------------------------------------------------------------
__global__ void k_edge1(int E) {
    int e = blockIdx.x * blockDim.x + threadIdx.x;
    if (e >= E) return;
    int s = g_src[e];
    int d = g_dst[e];
    float l = g_as[s] + g_ad[d];
    l = (l > 0.f) ? l : 0.2f * l;        // leaky_relu(0.2)
    g_logit[e] = l;
    if (l > 0.f)
        atomicMax((int*)&g_m[d], __float_as_int(l));
}

// ---------------------------------------------------------------------------
// K4: exp + fused {sum, deg} via one vectorized RED. Overwrites g_logit.
// ---------------------------------------------------------------------------
__global__ void k_edge2(int E) {
    int e = blockIdx.x * blockDim.x + threadIdx.x;
    if (e >= E) return;
    int d = g_dst[e];
    float el = __expf(g_logit[e] - g_m[d]);
    g_logit[e] = el;
    float* addr = (float*)&g_sumdeg[d];
    asm volatile("red.global.add.v2.f32 [%0], {%1, %2};"
                 :: "l"(addr), "f"(el), "f"(1.0f) : "memory");
}

// ---------------------------------------------------------------------------
// K5: per-node denom: denom = seg_sum + (E - deg) * exp(-m)
// ---------------------------------------------------------------------------
__global__ void k_node(int N, float Ef) {
    int i = blockIdx.x * blockDim.x + threadIdx.x;
    if (i >= N) return;
    float2 sd = g_sumdeg[i];
    float denom = sd.x + (Ef - sd.y) * __expf(-g_m[i]);
    g_invd[i] = 1.f / denom;
}

// ---------------------------------------------------------------------------
// K6: aggregation: out[dst] += w * h[src]
// 16 threads/edge, each owns one float4 chunk; vectorized RED scatter.
// ---------------------------------------------------------------------------
__global__ void k_agg(float* __restrict__ out, int E) {
    long long t = (long long)blockIdx.x * blockDim.x + threadIdx.x;
    int e = (int)(t >> 4);
    if (e >= E) return;
    int c = (int)(t & 15);
    int s = g_src[e];
    int d = g_dst[e];
    float w = g_logit[e] * g_invd[d];    // g_logit holds exp_l now
    const float4* h4 = (const float4*)g_h;
    float4 hv = h4[(size_t)s * 16 + c];
    float vx = w * hv.x, vy = w * hv.y, vz = w * hv.z, vw = w * hv.w;
    float* addr = out + (size_t)d * F_OUT + c * 4;
    asm volatile("red.global.add.v4.f32 [%0], {%1, %2, %3, %4};"
                 :: "l"(addr), "f"(vx), "f"(vy), "f"(vz), "f"(vw)
                 : "memory");
}

// ---------------------------------------------------------------------------
// K7: elementwise ELU over the output (float4 vectorized)
// ---------------------------------------------------------------------------
__global__ void k_elu(float* __restrict__ out, int n4) {
    int i = blockIdx.x * blockDim.x + threadIdx.x;
    if (i >= n4) return;
    float4 v = ((float4*)out)[i];
    v.x = (v.x > 0.f) ? v.x : expm1f(v.x);
    v.y = (v.y > 0.f) ? v.y : expm1f(v.y);
    v.z = (v.z > 0.f) ? v.z : expm1f(v.z);
    v.w = (v.w > 0.f) ? v.w : expm1f(v.w);
    ((float4*)out)[i] = v;
}

// ---------------------------------------------------------------------------
// Launch. Inputs identified by element count (robust to ordering):
//   x: N*128 = 6,400,000   edge_index: 2*E = 1,600,000   W: 8192   att: 128
// ---------------------------------------------------------------------------
extern "C" void kernel_launch(void* const* d_in, const int* in_sizes, int n_in,
                              void* d_out, int out_size) {
    int order[8];
    for (int i = 0; i < n_in; i++) order[i] = i;
    for (int i = 0; i < n_in; i++)
        for (int j = i + 1; j < n_in; j++)
            if (in_sizes[order[j]] > in_sizes[order[i]]) {
                int tmp = order[i]; order[i] = order[j]; order[j] = tmp;
            }
    const float* x   = (const float*)d_in[order[0]];
    const void*  ei  = (const void*) d_in[order[1]];
    const float* W   = (const float*)d_in[order[2]];
    const float* att = (const float*)d_in[order[3]];
    int N = in_sizes[order[0]] / F_IN;       // 50000
    int E = in_sizes[order[1]] / 2;          // 800000

    cudaMemsetAsync(d_out, 0, (size_t)out_size * sizeof(float));

    int gemm_smem = (F_IN * F_OUT + 64 * XS_PITCH) * (int)sizeof(float);  // 66.5KB
    static int attr_done = 0;
    if (!attr_done) {
        cudaFuncSetAttribute(k_gemm, cudaFuncAttributeMaxDynamicSharedMemorySize, gemm_smem);
        attr_done = 1;
    }

    k_zero  <<<(N + 255) / 256, 256>>>(N);
    k_detect<<<1, 256>>>((const unsigned int*)ei);
    k_norm  <<<(E + 255) / 256, 256>>>(ei, E);
    k_gemm  <<<(N + 127) / 128, 256, gemm_smem>>>(x, W, N);
    k_alpha <<<((N * 32) + 255) / 256, 256>>>(att, N);
    k_edge1 <<<(E + 255) / 256, 256>>>(E);
    k_edge2 <<<(E + 255) / 256, 256>>>(E);
    k_node  <<<(N + 255) / 256, 256>>>(N, (float)E);
    {
        long long total = (long long)E * 16;
        int blocks = (int)((total + 255) / 256);
        k_agg<<<blocks, 256>>>((float*)d_out, E);
    }
    k_elu   <<<((N * 16) + 255) / 256, 256>>>((float*)d_out, N * 16);
}

// round 6
// speedup vs baseline: 1.1236x; 1.1236x over previous
#include <cuda_runtime.h>
#include <cuda_bf16.h>
#include <cstdint>

#define NMAX 50000
#define EMAX 800000
#define F_IN 128
#define F_OUT 64
#define TILE_M 128

// ---- device scratch (no allocations allowed) ----
__device__ float g_h[NMAX * F_OUT];          // h = x @ W
__device__ float g_as[NMAX];                 // h . a1
__device__ float g_ad[NMAX];                 // h . a2
__device__ float g_m[NMAX];                  // max(seg_max, 0)
__device__ float g_sum[NMAX];                // segment sum of exp
__device__ float g_deg[NMAX];                // degree (float)
__device__ float g_invd[NMAX];               // 1/denom
__device__ float g_logit[EMAX];              // logit, then overwritten with exp_l
__device__ int   g_src[EMAX];                // normalized src indices (int32)
__device__ int   g_dst[EMAX];                // normalized dst indices (int32)
__device__ int   g_flag;                     // 0 = int64 edge buffer, nonzero = int32

// ============================ small kernels ============================
__global__ void k_zero(int N) {
    int i = blockIdx.x * blockDim.x + threadIdx.x;
    if (i == 0) g_flag = 0;
    if (i < N) {
        g_m[i] = 0.f;
        g_sum[i] = 0.f;
        g_deg[i] = 0.f;
    }
}

__global__ void k_detect(const unsigned int* __restrict__ raw) {
    int t = threadIdx.x;
    if (raw[2 * t + 1] != 0u) atomicOr(&g_flag, 1);
}

__global__ void k_norm(const void* __restrict__ raw, int E) {
    int e = blockIdx.x * blockDim.x + threadIdx.x;
    if (e >= E) return;
    int s, d;
    if (g_flag == 0) {
        const long long* p = (const long long*)raw;
        s = (int)p[e]; d = (int)p[E + e];
    } else {
        const int* p = (const int*)raw;
        s = p[e]; d = p[E + e];
    }
    g_src[e] = s;
    g_dst[e] = d;
}

// ============================ HMMA GEMM ============================
// h = x @ W via mma.sync m16n8k16 bf16, split precision (hi/lo, 3 passes).
// SMEM: A (x tile) [128 rows][128 k] bf16 hi+lo, row pitch 136 bf16 (272B);
//       B (W)      [128 k  ][64  n] bf16 hi+lo, row pitch 72 bf16 (144B).
// A fragments: ldmatrix.x4 (row-major).  B fragments: ldmatrix.x4.trans.
#define PA_B 272                 // A row pitch in bytes (136 bf16)
#define PB_B 144                 // B row pitch in bytes (72 bf16)
#define SM_A_HI 0
#define SM_A_LO (TILE_M * PA_B)              // 34816
#define SM_B_HI (SM_A_LO + TILE_M * PA_B)    // 69632
#define SM_B_LO (SM_B_HI + F_IN * PB_B)      // 88064
#define SM_TOTAL (SM_B_LO + F_IN * PB_B)     // 106496 (104 KB)

__device__ __forceinline__ uint32_t smem_u32(const void* p) {
    uint32_t a;
    asm("{ .reg .u64 t; cvta.to.shared.u64 t, %1; cvt.u32.u64 %0, t; }" : "=r"(a) : "l"(p));
    return a;
}

__device__ __forceinline__ void split2(float a, float b, uint32_t& hi, uint32_t& lo) {
    __nv_bfloat16 ah = __float2bfloat16(a);
    __nv_bfloat16 bh = __float2bfloat16(b);
    __nv_bfloat16 al = __float2bfloat16(a - __bfloat162float(ah));
    __nv_bfloat16 bl = __float2bfloat16(b - __bfloat162float(bh));
    hi = (uint32_t)__bfloat16_as_ushort(ah) | ((uint32_t)__bfloat16_as_ushort(bh) << 16);
    lo = (uint32_t)__bfloat16_as_ushort(al) | ((uint32_t)__bfloat16_as_ushort(bl) << 16);
}

#define LDSM_X4(r0, r1, r2, r3, addr) \
    asm volatile("ldmatrix.sync.aligned.m8n8.x4.shared.b16 {%0,%1,%2,%3}, [%4];" \
                 : "=r"(r0), "=r"(r1), "=r"(r2), "=r"(r3) : "r"(addr))
#define LDSM_X4T(r0, r1, r2, r3, addr) \
    asm volatile("ldmatrix.sync.aligned.m8n8.x4.trans.shared.b16 {%0,%1,%2,%3}, [%4];" \
                 : "=r"(r0), "=r"(r1), "=r"(r2), "=r"(r3) : "r"(addr))
#define MMA_BF16(d, a0, a1, a2, a3, b0, b1) \
    asm volatile("mma.sync.aligned.m16n8k16.row.col.f32.bf16.bf16.f32 " \
                 "{%0,%1,%2,%3}, {%4,%5,%6,%7}, {%8,%9}, {%0,%1,%2,%3};" \
                 : "+f"((d)[0]), "+f"((d)[1]), "+f"((d)[2]), "+f"((d)[3]) \
                 : "r"(a0), "r"(a1), "r"(a2), "r"(a3), "r"(b0), "r"(b1))

__global__ void __launch_bounds__(256, 2)
k_gemm_mma(const float* __restrict__ x, const float* __restrict__ W, int N) {
    extern __shared__ char smem[];
    uint32_t sb = smem_u32(smem);
    int tid = threadIdx.x;
    int wid = tid >> 5;
    int lane = tid & 31;
    int row0 = blockIdx.x * TILE_M;

    // ---- stage A: 128 rows x 16 k-chunks of 8 (2048 tasks) ----
    for (int i = tid; i < TILE_M * 16; i += 256) {
        int r = i >> 4, kc = i & 15;
        int gr = row0 + r;
        float f[8];
        if (gr < N) {
            float4 u = *(const float4*)&x[(size_t)gr * F_IN + kc * 8];
            float4 v = *(const float4*)&x[(size_t)gr * F_IN + kc * 8 + 4];
            f[0]=u.x; f[1]=u.y; f[2]=u.z; f[3]=u.w; f[4]=v.x; f[5]=v.y; f[6]=v.z; f[7]=v.w;
        } else {
            #pragma unroll
            for (int j = 0; j < 8; j++) f[j] = 0.f;
        }
        uint32_t hb[4], lb[4];
        #pragma unroll
        for (int j = 0; j < 4; j++) split2(f[2*j], f[2*j+1], hb[j], lb[j]);
        int off = r * PA_B + kc * 16;
        *(uint4*)(smem + SM_A_HI + off) = make_uint4(hb[0], hb[1], hb[2], hb[3]);
        *(uint4*)(smem + SM_A_LO + off) = make_uint4(lb[0], lb[1], lb[2], lb[3]);
    }

    // ---- stage B: W k-major, 128 k-rows x 8 n-chunks of 8 (1024 tasks) ----
    for (int i = tid; i < F_IN * 8; i += 256) {
        int k = i >> 3, nc = i & 7;
        float4 u = *(const float4*)&W[k * F_OUT + nc * 8];
        float4 v = *(const float4*)&W[k * F_OUT + nc * 8 + 4];
        float f[8] = {u.x, u.y, u.z, u.w, v.x, v.y, v.z, v.w};
        uint32_t hb[4], lb[4];
        #pragma unroll
        for (int j = 0; j < 4; j++) split2(f[2*j], f[2*j+1], hb[j], lb[j]);
        int off = k * PB_B + nc * 16;
        *(uint4*)(smem + SM_B_HI + off) = make_uint4(hb[0], hb[1], hb[2], hb[3]);
        *(uint4*)(smem + SM_B_LO + off) = make_uint4(lb[0], lb[1], lb[2], lb[3]);
    }
    __syncthreads();

    // ---- MMA mainloop: warp computes rows [16*wid, +16), all 64 cols ----
    int mi = lane >> 3;          // matrix index within ldmatrix.x4
    int wrow = lane & 7;
    // A lane address: row = 16*wid + wrow + (mi&1)*8, k-extra = (mi>>1)*8
    uint32_t aoff = (uint32_t)((16 * wid + wrow + (mi & 1) * 8) * PA_B + (mi >> 1) * 16);
    // B lane address: k-row = wrow + (mi&1)*8, n-extra = (mi>>1)*8
    uint32_t boff = (uint32_t)((wrow + (mi & 1) * 8) * PB_B + (mi >> 1) * 16);

    float d[8][4];
    #pragma unroll
    for (int i = 0; i < 8; i++)
        #pragma unroll
        for (int j = 0; j < 4; j++) d[i][j] = 0.f;

    #pragma unroll
    for (int p = 0; p < 3; p++) {
        uint32_t abase = sb + (p == 2 ? SM_A_LO : SM_A_HI) + aoff;
        uint32_t bbase = sb + (p == 1 ? SM_B_LO : SM_B_HI) + boff;
        #pragma unroll
        for (int ks = 0; ks < 8; ks++) {
            uint32_t a0, a1, a2, a3;
            LDSM_X4(a0, a1, a2, a3, abase + ks * 32);
            uint32_t bk = bbase + ks * 16 * PB_B;
            #pragma unroll
            for (int np = 0; np < 4; np++) {
                uint32_t b0, b1, b2, b3;
                LDSM_X4T(b0, b1, b2, b3, bk + np * 32);
                MMA_BF16(d[2 * np],     a0, a1, a2, a3, b0, b1);
                MMA_BF16(d[2 * np + 1], a0, a1, a2, a3, b2, b3);
            }
        }
    }

    // ---- epilogue: thread (g = lane>>2, tg = lane&3) holds cols tg*2,+1 of
    //      rows g and g+8 per 8-col group ----
    int g = lane >> 2, tg = lane & 3;
    int row_a = row0 + 16 * wid + g;
    int row_b = row_a + 8;
    #pragma unroll
    for (int ng = 0; ng < 8; ng++) {
        int col = ng * 8 + tg * 2;
        if (row_a < N)
            *(float2*)&g_h[(size_t)row_a * F_OUT + col] = make_float2(d[ng][0], d[ng][1]);
        if (row_b < N)
            *(float2*)&g_h[(size_t)row_b * F_OUT + col] = make_float2(d[ng][2], d[ng][3]);
    }
}

// ============================ rest of pipeline ============================
__global__ void k_alpha(const float* __restrict__ att, int N) {
    int gt = blockIdx.x * blockDim.x + threadIdx.x;
    int node = gt >> 5;
    int lane = gt & 31;
    if (node >= N) return;
    float2 hv = *(const float2*)&g_h[(size_t)node * F_OUT + lane * 2];
    float a1x = att[lane * 2], a1y = att[lane * 2 + 1];
    float a2x = att[F_OUT + lane * 2], a2y = att[F_OUT + lane * 2 + 1];
    float s = hv.x * a1x + hv.y * a1y;
    float d = hv.x * a2x + hv.y * a2y;
    #pragma unroll
    for (int o = 16; o; o >>= 1) {
        s += __shfl_down_sync(0xFFFFFFFFu, s, o);
        d += __shfl_down_sync(0xFFFFFFFFu, d, o);
    }
    if (lane == 0) { g_as[node] = s; g_ad[node] = d; }
}

__global__ void k_edge1(int E) {
    int e = blockIdx.x * blockDim.x + threadIdx.x;
    if (e >= E) return;
    int s = g_src[e];
    int d = g_dst[e];
    float l = g_as[s] + g_ad[d];
    l = (l > 0.f) ? l : 0.2f * l;        // leaky_relu(0.2)
    g_logit[e] = l;
    if (l > 0.f)
        atomicMax((int*)&g_m[d], __float_as_int(l));
}

__global__ void k_edge2(int E) {
    int e = blockIdx.x * blockDim.x + threadIdx.x;
    if (e >= E) return;
    int d = g_dst[e];
    float el = __expf(g_logit[e] - g_m[d]);
    g_logit[e] = el;
    atomicAdd(&g_sum[d], el);
    atomicAdd(&g_deg[d], 1.f);
}

__global__ void k_node(int N, float Ef) {
    int i = blockIdx.x * blockDim.x + threadIdx.x;
    if (i >= N) return;
    float denom = g_sum[i] + (Ef - g_deg[i]) * __expf(-g_m[i]);
    g_invd[i] = 1.f / denom;
}

__global__ void k_agg(float* __restrict__ out, int E) {
    long long t = (long long)blockIdx.x * blockDim.x + threadIdx.x;
    int e = (int)(t >> 4);
    if (e >= E) return;
    int c = (int)(t & 15);
    int s = g_src[e];
    int d = g_dst[e];
    float w = g_logit[e] * g_invd[d];    // g_logit holds exp_l now
    const float4* h4 = (const float4*)g_h;
    float4 hv = h4[(size_t)s * 16 + c];
    float vx = w * hv.x, vy = w * hv.y, vz = w * hv.z, vw = w * hv.w;
    float* addr = out + (size_t)d * F_OUT + c * 4;
    asm volatile("red.global.add.v4.f32 [%0], {%1, %2, %3, %4};"
                 :: "l"(addr), "f"(vx), "f"(vy), "f"(vz), "f"(vw)
                 : "memory");
}

__global__ void k_elu(float* __restrict__ out, int n4) {
    int i = blockIdx.x * blockDim.x + threadIdx.x;
    if (i >= n4) return;
    float4 v = ((float4*)out)[i];
    v.x = (v.x > 0.f) ? v.x : expm1f(v.x);
    v.y = (v.y > 0.f) ? v.y : expm1f(v.y);
    v.z = (v.z > 0.f) ? v.z : expm1f(v.z);
    v.w = (v.w > 0.f) ? v.w : expm1f(v.w);
    ((float4*)out)[i] = v;
}

// ---------------------------------------------------------------------------
extern "C" void kernel_launch(void* const* d_in, const int* in_sizes, int n_in,
                              void* d_out, int out_size) {
    int order[8];
    for (int i = 0; i < n_in; i++) order[i] = i;
    for (int i = 0; i < n_in; i++)
        for (int j = i + 1; j < n_in; j++)
            if (in_sizes[order[j]] > in_sizes[order[i]]) {
                int tmp = order[i]; order[i] = order[j]; order[j] = tmp;
            }
    const float* x   = (const float*)d_in[order[0]];
    const void*  ei  = (const void*) d_in[order[1]];
    const float* W   = (const float*)d_in[order[2]];
    const float* att = (const float*)d_in[order[3]];
    int N = in_sizes[order[0]] / F_IN;       // 50000
    int E = in_sizes[order[1]] / 2;          // 800000

    cudaMemsetAsync(d_out, 0, (size_t)out_size * sizeof(float));

    static int attr_done = 0;
    if (!attr_done) {
        cudaFuncSetAttribute(k_gemm_mma, cudaFuncAttributeMaxDynamicSharedMemorySize, SM_TOTAL);
        attr_done = 1;
    }

    k_zero    <<<(N + 255) / 256, 256>>>(N);
    k_detect  <<<1, 256>>>((const unsigned int*)ei);
    k_norm    <<<(E + 255) / 256, 256>>>(ei, E);
    k_gemm_mma<<<(N + TILE_M - 1) / TILE_M, 256, SM_TOTAL>>>(x, W, N);
    k_alpha   <<<((N * 32) + 255) / 256, 256>>>(att, N);
    k_edge1   <<<(E + 255) / 256, 256>>>(E);
    k_edge2   <<<(E + 255) / 256, 256>>>(E);
    k_node    <<<(N + 255) / 256, 256>>>(N, (float)E);
    {
        long long total = (long long)E * 16;
        int blocks = (int)((total + 255) / 256);
        k_agg<<<blocks, 256>>>((float*)d_out, E);
    }
    k_elu     <<<((N * 16) + 255) / 256, 256>>>((float*)d_out, N * 16);
}